// round 1
// baseline (speedup 1.0000x reference)
#include <cuda_runtime.h>
#include <math.h>

#define KC 192
#define Q_MIN 0.5f

// ---------------- device scratch (no allocations allowed) ----------------

// Per-cluster accumulator padded to 1024B so each cluster's atomics land in a
// distinct L2 slice region (hash uses bits {8,10-27}); avoids same-slice
// serialization of 150K atomic adds onto a 768B array.
struct ClusterAcc {
    unsigned long long key;   // (beta_bits << 32) | (0xFFFFFFFF - idx)  -> argmax beta, tie = smallest idx
    float wsum;               // sum of w = atanh(beta)^2 over members
    float wp0;                // sum of w * energy_loss
    float wp1;                // sum of w * position_loss
    char pad[1024 - 8 - 12];
};
__device__ ClusterAcc g_acc[KC];

__device__ float4 g_xq[KC];   // x_alpha (xyz) + q_alpha (0 if cluster doesn't exist)

// scalars: 0=att_sum 1=rep_sum 2=minb_sum 3=pay_sum 4=noise_sum 5=noise_cnt 6=nobj
__device__ float g_s[8];

// ---------------- helpers ----------------

__device__ __forceinline__ float warp_sum(float v) {
    #pragma unroll
    for (int o = 16; o > 0; o >>= 1) v += __shfl_down_sync(0xFFFFFFFFu, v, o);
    return v;
}

__device__ __forceinline__ float clip_beta(float b) {
    return fminf(fmaxf(b, 1e-4f), 1.0f - 1e-4f);
}

// ---------------- kernels ----------------

__global__ void k_init() {
    int j = threadIdx.x;
    if (j < KC) {
        g_acc[j].key  = 0ull;
        g_acc[j].wsum = 0.0f;
        g_acc[j].wp0  = 0.0f;
        g_acc[j].wp1  = 0.0f;
    }
    if (j < 8) g_s[j] = 0.0f;
}

// Pass 1: per-point cluster reductions + noise sums.
__global__ void k_pass1(const float* __restrict__ pbeta,
                        const float* __restrict__ tenergy,
                        const float* __restrict__ penergy,
                        const float* __restrict__ tpos,
                        const float* __restrict__ ppos,
                        const int*   __restrict__ tidx,
                        int n)
{
    int i = blockIdx.x * blockDim.x + threadIdx.x;
    if (i >= n) return;
    float b = clip_beta(pbeta[i]);
    int k = tidx[i];
    if (k >= 0) {
        float a = atanhf(b);
        float w = a * a;
        unsigned long long key =
            ((unsigned long long)__float_as_uint(b) << 32) |
            (unsigned long long)(0xFFFFFFFFu - (unsigned)i);
        atomicMax(&g_acc[k].key, key);
        atomicAdd(&g_acc[k].wsum, w);

        float te = tenergy[i], pe = penergy[i];
        float de = te - pe;
        float el = (de * de) / (te * te);

        float tp0 = tpos[2 * i], tp1 = tpos[2 * i + 1];
        float pp0 = ppos[2 * i], pp1 = ppos[2 * i + 1];
        float d0 = tp0 - pp0, d1 = tp1 - pp1;
        float pl = (d0 * d0) / (tp0 * tp0) + (d1 * d1) / (tp1 * tp1);

        atomicAdd(&g_acc[k].wp0, w * el);
        atomicAdd(&g_acc[k].wp1, w * pl);
    } else {
        atomicAdd(&g_s[4], b);
        atomicAdd(&g_s[5], 1.0f);
    }
}

// Pass 2: per-cluster gather + min_b / pay / n_obj reduction. One block, 192 threads.
__global__ void k_cluster(const float* __restrict__ pbeta,
                          const float* __restrict__ cc,
                          const float* __restrict__ ttime)
{
    int k = threadIdx.x;
    float minb = 0.0f, pay = 0.0f, nobj = 0.0f;
    if (k < KC) {
        unsigned long long key = g_acc[k].key;
        float4 xq = make_float4(0.0f, 0.0f, 0.0f, 0.0f);
        if (key != 0ull) {
            unsigned idx = 0xFFFFFFFFu - (unsigned)(key & 0xFFFFFFFFull);
            float b = clip_beta(pbeta[idx]);
            float a = atanhf(b);
            float q = (a * a + Q_MIN) * ttime[idx];
            xq = make_float4(cc[3 * idx], cc[3 * idx + 1], cc[3 * idx + 2], q);
            nobj = 1.0f;
            minb = 1.0f - b;
            float ws = g_acc[k].wsum + 1e-9f;
            pay = (g_acc[k].wp0 + g_acc[k].wp1) / ws;
        }
        g_xq[k] = xq;
    }
    // reduce minb, pay, nobj over 6 warps
    __shared__ float red[3][6];
    float wm = warp_sum(minb), wp = warp_sum(pay), wn = warp_sum(nobj);
    int wid = threadIdx.x >> 5, lid = threadIdx.x & 31;
    if (lid == 0) { red[0][wid] = wm; red[1][wid] = wp; red[2][wid] = wn; }
    __syncthreads();
    if (wid == 0) {
        float vm = (lid < 6) ? red[0][lid] : 0.0f;
        float vp = (lid < 6) ? red[1][lid] : 0.0f;
        float vn = (lid < 6) ? red[2][lid] : 0.0f;
        vm = warp_sum(vm); vp = warp_sum(vp); vn = warp_sum(vn);
        if (lid == 0) { g_s[2] = vm; g_s[3] = vp; g_s[6] = vn; }
    }
}

// Pass 3: the O(N*K) attraction/repulsion pass.
__global__ void __launch_bounds__(256) k_main(const float* __restrict__ pbeta,
                                              const float* __restrict__ cc,
                                              const float* __restrict__ ttime,
                                              const int*   __restrict__ tidx,
                                              int n)
{
    __shared__ float4 sxq[KC];
    int t = threadIdx.x;
    for (int j = t; j < KC; j += blockDim.x) sxq[j] = g_xq[j];
    __syncthreads();

    int i = blockIdx.x * blockDim.x + t;
    float att = 0.0f, rep = 0.0f;
    if (i < n) {
        float x0 = cc[3 * i], x1 = cc[3 * i + 1], x2 = cc[3 * i + 2];
        float b = clip_beta(pbeta[i]);
        float a = atanhf(b);
        float q = (a * a + Q_MIN) * ttime[i];

        float hacc = 0.0f;
        #pragma unroll 4
        for (int k = 0; k < KC; k++) {
            float4 A = sxq[k];
            float dx = x0 - A.x, dy = x1 - A.y, dz = x2 - A.z;
            float d2 = fmaf(dx, dx, fmaf(dy, dy, dz * dz));
            float tt = d2 + 1e-9f;
            if (tt < 1.0f) hacc += A.w * (1.0f - tt * rsqrtf(tt));
        }
        int k = tidx[i];
        if (k >= 0) {
            float4 A = sxq[k];
            float dx = x0 - A.x, dy = x1 - A.y, dz = x2 - A.z;
            float d2 = fmaf(dx, dx, fmaf(dy, dy, dz * dz));
            att = d2 * A.w * q;                   // member attraction (obj exists by construction)
            float tt = d2 + 1e-9f;
            if (tt < 1.0f) hacc -= A.w * (1.0f - tt * rsqrtf(tt));  // exclude member from repulsion
        }
        rep = q * hacc;
    }

    // block reduce (8 warps)
    __shared__ float red[16];
    float wa = warp_sum(att), wr = warp_sum(rep);
    int wid = t >> 5, lid = t & 31;
    if (lid == 0) { red[wid] = wa; red[8 + wid] = wr; }
    __syncthreads();
    if (wid == 0) {
        float va = (lid < 8) ? red[lid]     : 0.0f;
        float vr = (lid < 8) ? red[8 + lid] : 0.0f;
        va = warp_sum(va); vr = warp_sum(vr);
        if (lid == 0) { atomicAdd(&g_s[0], va); atomicAdd(&g_s[1], vr); }
    }
}

__global__ void k_final(float* out, float inv_n) {
    float nobj = fmaxf(g_s[6], 1.0f);
    float ncnt = fmaxf(g_s[5], 1.0f);
    out[0] = (g_s[0] + g_s[1]) * inv_n      // att + rep
           + g_s[2] / nobj                  // min_b
           + g_s[4] / ncnt                  // noise (S_B = 1)
           + g_s[3] / nobj;                 // pay[0] + pay[1]
}

// ---------------- launcher ----------------
// metadata order: 0 pred_beta, 1 pred_ccoords, 2 pred_energy, 3 pred_pos,
// 4 pred_time, 5 pred_id, 6 t_idx, 7 t_energy, 8 t_pos, 9 t_time, 10 t_pid, 11 rowsplits
extern "C" void kernel_launch(void* const* d_in, const int* in_sizes, int n_in,
                              void* d_out, int out_size) {
    const float* pbeta   = (const float*)d_in[0];
    const float* cc      = (const float*)d_in[1];
    const float* penergy = (const float*)d_in[2];
    const float* ppos    = (const float*)d_in[3];
    const int*   tidx    = (const int*)  d_in[6];
    const float* tenergy = (const float*)d_in[7];
    const float* tpos    = (const float*)d_in[8];
    const float* ttime   = (const float*)d_in[9];
    float* out = (float*)d_out;

    int n = in_sizes[0];
    int blocks = (n + 255) / 256;

    k_init<<<1, 256>>>();
    k_pass1<<<blocks, 256>>>(pbeta, tenergy, penergy, tpos, ppos, tidx, n);
    k_cluster<<<1, KC>>>(pbeta, cc, ttime);
    k_main<<<blocks, 256>>>(pbeta, cc, ttime, tidx, n);
    k_final<<<1, 1>>>(out, 1.0f / (float)n);
}

// round 2
// speedup vs baseline: 1.1155x; 1.1155x over previous
#include <cuda_runtime.h>
#include <math.h>

#define KC 192
#define Q_MIN 0.5f
#define TPB1 256
#define NB3 296
#define TPB3 256
#define NT3 (NB3 * TPB3)   // 75776 threads, 2 points each -> covers 151552 >= 150000

// ---------------- device scratch (no allocations allowed) ----------------

// 1024B-padded per-cluster accumulator: atomics land in distinct L2 regions.
struct ClusterAcc {
    unsigned long long key;   // (beta_bits << 32) | (0xFFFFFFFF - idx)
    float wsum, wp0, wp1;
    char pad[1024 - 20];
};
__device__ ClusterAcc g_acc[KC];

__device__ ulonglong2 g_B[KC * 2];  // per cluster: {{Bx,Bx},{By,By}}, {{Bz,Bz},{Bw,Bw}}  (f32x2 duplicated)
__device__ float4     g_Bs[KC];     // scalar {Bx,By,Bz,Bw} for member recompute
__device__ float      g_q[KC];      // q_alpha (0 if cluster empty)

// 0 att, 1 rep, 2 minb, 3 pay, 4 noise_sum, 5 noise_cnt, 6 nobj, 7 Qsum
__device__ float g_s[8];
__device__ unsigned g_done;

// ---------------- helpers ----------------

__device__ __forceinline__ float warp_sum(float v) {
    #pragma unroll
    for (int o = 16; o > 0; o >>= 1) v += __shfl_down_sync(0xFFFFFFFFu, v, o);
    return v;
}
__device__ __forceinline__ float clip_beta(float b) {
    return fminf(fmaxf(b, 1e-4f), 1.0f - 1e-4f);
}
__device__ __forceinline__ unsigned long long fma2(unsigned long long a, unsigned long long b, unsigned long long c) {
    unsigned long long d;
    asm("fma.rn.f32x2 %0, %1, %2, %3;" : "=l"(d) : "l"(a), "l"(b), "l"(c));
    return d;
}
__device__ __forceinline__ unsigned long long add2(unsigned long long a, unsigned long long b) {
    unsigned long long d;
    asm("add.rn.f32x2 %0, %1, %2;" : "=l"(d) : "l"(a), "l"(b));
    return d;
}
__device__ __forceinline__ unsigned long long packf2(float lo, float hi) {
    return (unsigned long long)__float_as_uint(lo) | ((unsigned long long)__float_as_uint(hi) << 32);
}
__device__ __forceinline__ unsigned long long dup2(float f) {
    unsigned long long u = (unsigned long long)__float_as_uint(f);
    return u | (u << 32);
}
__device__ __forceinline__ float lo32(unsigned long long v) { return __uint_as_float((unsigned)v); }
__device__ __forceinline__ float hi32(unsigned long long v) { return __uint_as_float((unsigned)(v >> 32)); }
__device__ __forceinline__ float fsqrt_ap(float x) {
    float r; asm("sqrt.approx.f32 %0, %1;" : "=f"(r) : "f"(x)); return r;
}

// ---------------- pass 1: per-point cluster reductions + noise ----------------
// g_acc / g_s[4,5] are zero on entry (zero-init at load; re-zeroed by k_main's finisher each launch).
__global__ void k_pass1(const float* __restrict__ pbeta,
                        const float* __restrict__ tenergy,
                        const float* __restrict__ penergy,
                        const float* __restrict__ tpos,
                        const float* __restrict__ ppos,
                        const int*   __restrict__ tidx,
                        int n)
{
    int i = blockIdx.x * blockDim.x + threadIdx.x;
    if (i >= n) return;
    float b = clip_beta(pbeta[i]);
    int k = tidx[i];
    if (k >= 0) {
        float a = atanhf(b);
        float w = a * a;
        unsigned long long key =
            ((unsigned long long)__float_as_uint(b) << 32) |
            (unsigned long long)(0xFFFFFFFFu - (unsigned)i);
        atomicMax(&g_acc[k].key, key);
        atomicAdd(&g_acc[k].wsum, w);

        float te = tenergy[i], pe = penergy[i];
        float de = te - pe;
        float el = (de * de) / (te * te);

        float2 tp = ((const float2*)tpos)[i];
        float2 pp = ((const float2*)ppos)[i];
        float d0 = tp.x - pp.x, d1 = tp.y - pp.y;
        float pl = (d0 * d0) / (tp.x * tp.x) + (d1 * d1) / (tp.y * tp.y);

        atomicAdd(&g_acc[k].wp0, w * el);
        atomicAdd(&g_acc[k].wp1, w * pl);
    } else {
        atomicAdd(&g_s[4], b);
        atomicAdd(&g_s[5], 1.0f);
    }
}

// ---------------- pass 2: per-cluster alpha gather + packed-B build ----------------
__global__ void k_cluster(const float* __restrict__ pbeta,
                          const float* __restrict__ cc,
                          const float* __restrict__ ttime)
{
    int k = threadIdx.x;
    float minb = 0.0f, pay = 0.0f, nobj = 0.0f, qs = 0.0f;
    if (k < KC) {
        unsigned long long key = g_acc[k].key;
        float Bx = 0.f, By = 0.f, Bz = 0.f, Bw = 0.f, q = 0.f;
        if (key != 0ull) {
            unsigned idx = 0xFFFFFFFFu - (unsigned)(key & 0xFFFFFFFFull);
            float b = clip_beta(pbeta[idx]);
            float a = atanhf(b);
            q = (a * a + Q_MIN) * ttime[idx];
            float ax = cc[3 * idx], ay = cc[3 * idx + 1], az = cc[3 * idx + 2];
            Bx = -2.0f * ax; By = -2.0f * ay; Bz = -2.0f * az;
            Bw = ax * ax + ay * ay + az * az;
            nobj = 1.0f;
            minb = 1.0f - b;
            qs = q;
            pay = (g_acc[k].wp0 + g_acc[k].wp1) / (g_acc[k].wsum + 1e-9f);
        }
        g_B[2 * k]     = make_ulonglong2(dup2(Bx), dup2(By));
        g_B[2 * k + 1] = make_ulonglong2(dup2(Bz), dup2(Bw));
        g_Bs[k] = make_float4(Bx, By, Bz, Bw);
        g_q[k] = q;
    }
    // reduce minb / pay / nobj / Qsum over 6 warps
    __shared__ float red[4][6];
    float wm = warp_sum(minb), wp = warp_sum(pay), wn = warp_sum(nobj), wq = warp_sum(qs);
    int wid = threadIdx.x >> 5, lid = threadIdx.x & 31;
    if (lid == 0) { red[0][wid] = wm; red[1][wid] = wp; red[2][wid] = wn; red[3][wid] = wq; }
    __syncthreads();
    if (wid == 0) {
        float vm = (lid < 6) ? red[0][lid] : 0.0f;
        float vp = (lid < 6) ? red[1][lid] : 0.0f;
        float vn = (lid < 6) ? red[2][lid] : 0.0f;
        float vq = (lid < 6) ? red[3][lid] : 0.0f;
        vm = warp_sum(vm); vp = warp_sum(vp); vn = warp_sum(vn); vq = warp_sum(vq);
        if (lid == 0) { g_s[2] = vm; g_s[3] = vp; g_s[6] = vn; g_s[7] = vq; }
    }
}

// ---------------- pass 3: O(N*K) pair pass, fused finisher + scratch reset ----------------
__global__ void __launch_bounds__(TPB3) k_main(const float* __restrict__ pbeta,
                                               const float* __restrict__ cc,
                                               const float* __restrict__ ttime,
                                               const int*   __restrict__ tidx,
                                               int n, float* __restrict__ out)
{
    __shared__ ulonglong2 sB[KC * 2];
    __shared__ float4 sBs[KC];
    __shared__ float sQ[KC];
    __shared__ float sQsum;
    __shared__ float red[16];
    __shared__ int sLast;

    int t = threadIdx.x;
    for (int j = t; j < KC * 2; j += TPB3) sB[j] = g_B[j];
    for (int j = t; j < KC; j += TPB3) { sBs[j] = g_Bs[j]; sQ[j] = g_q[j]; }
    if (t == 0) sQsum = g_s[7];
    __syncthreads();

    int i0 = blockIdx.x * TPB3 + t;
    int i1 = i0 + NT3;

    float x00 = 0.f, x01 = 0.f, x02 = 0.f, q0 = 0.f; int k0 = -1;
    float x10 = 0.f, x11 = 0.f, x12 = 0.f, q1 = 0.f; int k1 = -1;
    if (i0 < n) {
        x00 = cc[3 * i0]; x01 = cc[3 * i0 + 1]; x02 = cc[3 * i0 + 2];
        float b = clip_beta(pbeta[i0]); float a = atanhf(b);
        q0 = (a * a + Q_MIN) * ttime[i0];
        k0 = tidx[i0];
    }
    if (i1 < n) {
        x10 = cc[3 * i1]; x11 = cc[3 * i1 + 1]; x12 = cc[3 * i1 + 2];
        float b = clip_beta(pbeta[i1]); float a = atanhf(b);
        q1 = (a * a + Q_MIN) * ttime[i1];
        k1 = tidx[i1];
    }
    float cie0 = fmaf(x02, x02, fmaf(x01, x01, fmaf(x00, x00, 1e-9f)));
    float cie1 = fmaf(x12, x12, fmaf(x11, x11, fmaf(x10, x10, 1e-9f)));

    unsigned long long x0p = packf2(x00, x10);
    unsigned long long x1p = packf2(x01, x11);
    unsigned long long x2p = packf2(x02, x12);
    unsigned long long cip = packf2(cie0, cie1);

    float acc0 = 0.0f, acc1 = 0.0f;
    #pragma unroll 4
    for (int k = 0; k < KC; k++) {
        ulonglong2 b0 = sB[2 * k];        // {Bx,Bx},{By,By}
        ulonglong2 b1 = sB[2 * k + 1];    // {Bz,Bz},{Bw,Bw}
        float qk = sQ[k];
        unsigned long long tt = fma2(b0.x, x0p, cip);
        tt = fma2(b0.y, x1p, tt);
        tt = fma2(b1.x, x2p, tt);
        unsigned long long d2p = add2(tt, b1.y);
        float s0 = fsqrt_ap(lo32(d2p));
        float s1 = fsqrt_ap(hi32(d2p));
        acc0 = fmaf(qk, fminf(s0, 1.0f), acc0);
        acc1 = fmaf(qk, fminf(s1, 1.0f), acc1);
    }

    float Qsum = sQsum;
    float att = 0.0f, rep = 0.0f;
    {
        float def = Qsum - acc0;
        if (k0 >= 0) {
            float4 Bm = sBs[k0]; float qm = sQ[k0];
            float tm = fmaf(Bm.x, x00, cie0); tm = fmaf(Bm.y, x01, tm); tm = fmaf(Bm.z, x02, tm);
            float d2e = tm + Bm.w;
            float m = fminf(fsqrt_ap(d2e), 1.0f);
            def -= qm * (1.0f - m);
            att += (d2e - 1e-9f) * qm * q0;
        }
        rep += q0 * def;
    }
    {
        float def = Qsum - acc1;
        if (k1 >= 0) {
            float4 Bm = sBs[k1]; float qm = sQ[k1];
            float tm = fmaf(Bm.x, x10, cie1); tm = fmaf(Bm.y, x11, tm); tm = fmaf(Bm.z, x12, tm);
            float d2e = tm + Bm.w;
            float m = fminf(fsqrt_ap(d2e), 1.0f);
            def -= qm * (1.0f - m);
            att += (d2e - 1e-9f) * qm * q1;
        }
        rep += q1 * def;
    }

    // block reduce (8 warps)
    float wa = warp_sum(att), wr = warp_sum(rep);
    int wid = t >> 5, lid = t & 31;
    if (lid == 0) { red[wid] = wa; red[8 + wid] = wr; }
    __syncthreads();
    if (wid == 0) {
        float va = (lid < 8) ? red[lid]     : 0.0f;
        float vr = (lid < 8) ? red[8 + lid] : 0.0f;
        va = warp_sum(va); vr = warp_sum(vr);
        if (lid == 0) { atomicAdd(&g_s[0], va); atomicAdd(&g_s[1], vr); }
    }

    // finisher: last block computes output and re-zeros all scratch for the next replay
    if (t == 0) {
        __threadfence();
        unsigned old = atomicAdd(&g_done, 1u);
        sLast = (old == gridDim.x - 1) ? 1 : 0;
    }
    __syncthreads();
    if (sLast) {
        if (t == 0) {
            __threadfence();
            volatile float* vs = g_s;
            float s0 = vs[0], s1 = vs[1], s2 = vs[2], s3 = vs[3];
            float s4 = vs[4], s5 = vs[5], s6 = vs[6];
            float nobj = fmaxf(s6, 1.0f);
            float ncnt = fmaxf(s5, 1.0f);
            out[0] = (s0 + s1) / (float)n + s2 / nobj + s4 / ncnt + s3 / nobj;
        }
        __syncthreads();
        for (int j = t; j < KC; j += TPB3) {
            g_acc[j].key = 0ull; g_acc[j].wsum = 0.0f;
            g_acc[j].wp0 = 0.0f; g_acc[j].wp1 = 0.0f;
        }
        if (t < 8) g_s[t] = 0.0f;
        if (t == 0) g_done = 0u;
    }
}

// ---------------- launcher ----------------
// metadata order: 0 pred_beta, 1 pred_ccoords, 2 pred_energy, 3 pred_pos,
// 4 pred_time, 5 pred_id, 6 t_idx, 7 t_energy, 8 t_pos, 9 t_time, 10 t_pid, 11 rowsplits
extern "C" void kernel_launch(void* const* d_in, const int* in_sizes, int n_in,
                              void* d_out, int out_size) {
    const float* pbeta   = (const float*)d_in[0];
    const float* cc      = (const float*)d_in[1];
    const float* penergy = (const float*)d_in[2];
    const float* ppos    = (const float*)d_in[3];
    const int*   tidx    = (const int*)  d_in[6];
    const float* tenergy = (const float*)d_in[7];
    const float* tpos    = (const float*)d_in[8];
    const float* ttime   = (const float*)d_in[9];
    float* out = (float*)d_out;

    int n = in_sizes[0];
    int blocks1 = (n + TPB1 - 1) / TPB1;

    k_pass1<<<blocks1, TPB1>>>(pbeta, tenergy, penergy, tpos, ppos, tidx, n);
    k_cluster<<<1, KC>>>(pbeta, cc, ttime);
    k_main<<<NB3, TPB3>>>(pbeta, cc, ttime, tidx, n, out);
}

// round 3
// speedup vs baseline: 1.2252x; 1.0983x over previous
#include <cuda_runtime.h>
#include <math.h>

#define KC 192
#define Q_MIN 0.5f
#define TPB1 256
#define NB3 296
#define TPB3 256
#define NT3 (NB3 * TPB3)   // 75776 threads, 2 points each -> covers 151552 >= 150000

// ---------------- device scratch (no allocations allowed) ----------------
// Each atomic target gets its own 1024B-strided slot so every accumulator
// lands on a distinct L2 partition (slice hash uses bits {8,10-27}).
__device__ unsigned long long g_key[KC * 128];   // stride 128 ull = 1024B
__device__ float g_wsum[KC * 256];               // stride 256 f32 = 1024B
__device__ float g_wps [KC * 256];
__device__ float g_nacc[32 * 256];               // 32 noise slots: [s*256]=sum, [s*256+1]=cnt

__device__ ulonglong2 g_B[KC * 2];  // per cluster: {{Bx,Bx},{By,By}}, {{Bz,Bz},{Bw,Bw}} (f32x2 dup)
__device__ float4     g_Bs[KC];     // scalar {Bx,By,Bz,Bw}
__device__ float      g_q[KC];      // q_alpha (0 if cluster empty)

// 0 att, 1 rep, 2 minb, 3 pay, 4 noise_sum, 5 noise_cnt, 6 nobj, 7 Qsum
__device__ float g_s[8];
__device__ unsigned g_done1, g_done2;

// ---------------- helpers ----------------
__device__ __forceinline__ float warp_sum(float v) {
    #pragma unroll
    for (int o = 16; o > 0; o >>= 1) v += __shfl_down_sync(0xFFFFFFFFu, v, o);
    return v;
}
__device__ __forceinline__ float clip_beta(float b) {
    return fminf(fmaxf(b, 1e-4f), 1.0f - 1e-4f);
}
__device__ __forceinline__ unsigned long long fma2(unsigned long long a, unsigned long long b, unsigned long long c) {
    unsigned long long d;
    asm("fma.rn.f32x2 %0, %1, %2, %3;" : "=l"(d) : "l"(a), "l"(b), "l"(c));
    return d;
}
__device__ __forceinline__ unsigned long long add2(unsigned long long a, unsigned long long b) {
    unsigned long long d;
    asm("add.rn.f32x2 %0, %1, %2;" : "=l"(d) : "l"(a), "l"(b));
    return d;
}
__device__ __forceinline__ unsigned long long packf2(float lo, float hi) {
    return (unsigned long long)__float_as_uint(lo) | ((unsigned long long)__float_as_uint(hi) << 32);
}
__device__ __forceinline__ unsigned long long dup2(float f) {
    unsigned long long u = (unsigned long long)__float_as_uint(f);
    return u | (u << 32);
}
__device__ __forceinline__ float lo32(unsigned long long v) { return __uint_as_float((unsigned)v); }
__device__ __forceinline__ float hi32(unsigned long long v) { return __uint_as_float((unsigned)(v >> 32)); }
__device__ __forceinline__ float fsqrt_ap(float x) {
    float r; asm("sqrt.approx.f32 %0, %1;" : "=f"(r) : "f"(x)); return r;
}

// ---------------- pass 1: per-point reductions + fused cluster stage ----------------
// Scratch (g_key/g_wsum/g_wps/g_nacc/g_done1) is zero on entry (zero-init at load,
// self-reset by this kernel's finisher each launch).
__global__ void __launch_bounds__(TPB1) k_pass1(const float* __restrict__ pbeta,
                        const float* __restrict__ tenergy,
                        const float* __restrict__ penergy,
                        const float* __restrict__ tpos,
                        const float* __restrict__ ppos,
                        const int*   __restrict__ tidx,
                        const float* __restrict__ cc,
                        const float* __restrict__ ttime,
                        int n)
{
    int t = threadIdx.x;
    int i = blockIdx.x * TPB1 + t;
    float nsum = 0.0f, ncnt = 0.0f;
    if (i < n) {
        float b = clip_beta(pbeta[i]);
        int k = tidx[i];
        if (k >= 0) {
            float a = atanhf(b);
            float w = a * a;
            unsigned long long key =
                ((unsigned long long)__float_as_uint(b) << 32) |
                (unsigned long long)(0xFFFFFFFFu - (unsigned)i);
            atomicMax(&g_key[k * 128], key);
            atomicAdd(&g_wsum[k * 256], w);

            float te = tenergy[i], pe = penergy[i];
            float de = te - pe;
            float el = (de * de) / (te * te);

            float2 tp = ((const float2*)tpos)[i];
            float2 pp = ((const float2*)ppos)[i];
            float d0 = tp.x - pp.x, d1 = tp.y - pp.y;
            float pl = (d0 * d0) / (tp.x * tp.x) + (d1 * d1) / (tp.y * tp.y);

            atomicAdd(&g_wps[k * 256], w * (el + pl));
        } else {
            nsum = b; ncnt = 1.0f;
        }
    }

    // block-reduce noise, scatter to 32 padded slots
    __shared__ float nred[2][8];
    {
        float ws = warp_sum(nsum), wc = warp_sum(ncnt);
        int wid = t >> 5, lid = t & 31;
        if (lid == 0) { nred[0][wid] = ws; nred[1][wid] = wc; }
        __syncthreads();
        if (wid == 0) {
            float vs = (lid < 8) ? nred[0][lid] : 0.0f;
            float vc = (lid < 8) ? nred[1][lid] : 0.0f;
            vs = warp_sum(vs); vc = warp_sum(vc);
            if (lid == 0 && (vs != 0.0f || vc != 0.0f)) {
                int s = (blockIdx.x & 31) * 256;
                atomicAdd(&g_nacc[s], vs);
                atomicAdd(&g_nacc[s + 1], vc);
            }
        }
    }

    // finisher block: fused k_cluster
    __shared__ int sLast;
    if (t == 0) {
        __threadfence();
        unsigned old = atomicAdd(&g_done1, 1u);
        sLast = (old == gridDim.x - 1) ? 1 : 0;
    }
    __syncthreads();
    if (!sLast) return;
    if (t == 0) __threadfence();
    __syncthreads();

    float minb = 0.0f, pay = 0.0f, nobj = 0.0f, qs = 0.0f;
    if (t < KC) {
        unsigned long long key = g_key[t * 128];
        float Bx = 0.f, By = 0.f, Bz = 0.f, Bw = 0.f, q = 0.f;
        if (key != 0ull) {
            unsigned idx = 0xFFFFFFFFu - (unsigned)(key & 0xFFFFFFFFull);
            float b = clip_beta(pbeta[idx]);
            float a = atanhf(b);
            q = (a * a + Q_MIN) * ttime[idx];
            float ax = cc[3 * idx], ay = cc[3 * idx + 1], az = cc[3 * idx + 2];
            Bx = -2.0f * ax; By = -2.0f * ay; Bz = -2.0f * az;
            Bw = ax * ax + ay * ay + az * az;
            nobj = 1.0f;
            minb = 1.0f - b;
            qs = q;
            pay = g_wps[t * 256] / (g_wsum[t * 256] + 1e-9f);
        }
        g_B[2 * t]     = make_ulonglong2(dup2(Bx), dup2(By));
        g_B[2 * t + 1] = make_ulonglong2(dup2(Bz), dup2(Bw));
        g_Bs[t] = make_float4(Bx, By, Bz, Bw);
        g_q[t] = q;
        // reset pass-1 scratch for next replay
        g_key[t * 128] = 0ull;
        g_wsum[t * 256] = 0.0f;
        g_wps[t * 256] = 0.0f;
    }
    // noise slot aggregation + reset (warp covering t in [0,32))
    if (t < 32) {
        float vs = g_nacc[t * 256];
        float vc = g_nacc[t * 256 + 1];
        g_nacc[t * 256] = 0.0f;
        g_nacc[t * 256 + 1] = 0.0f;
        vs = warp_sum(vs); vc = warp_sum(vc);
        if (t == 0) { g_s[4] = vs; g_s[5] = vc; g_done1 = 0u; }
    }
    // reduce minb / pay / nobj / Qsum over 8 warps
    __shared__ float red[4][8];
    float wm = warp_sum(minb), wp = warp_sum(pay), wn = warp_sum(nobj), wq = warp_sum(qs);
    int wid = t >> 5, lid = t & 31;
    if (lid == 0) { red[0][wid] = wm; red[1][wid] = wp; red[2][wid] = wn; red[3][wid] = wq; }
    __syncthreads();
    if (wid == 0) {
        float vm = (lid < 8) ? red[0][lid] : 0.0f;
        float vp = (lid < 8) ? red[1][lid] : 0.0f;
        float vn = (lid < 8) ? red[2][lid] : 0.0f;
        float vq = (lid < 8) ? red[3][lid] : 0.0f;
        vm = warp_sum(vm); vp = warp_sum(vp); vn = warp_sum(vn); vq = warp_sum(vq);
        if (lid == 0) { g_s[2] = vm; g_s[3] = vp; g_s[6] = vn; g_s[7] = vq; }
    }
}

// ---------------- pass 2: O(N*K) pair pass, fused finisher + scratch reset ----------------
__global__ void __launch_bounds__(TPB3) k_main(const float* __restrict__ pbeta,
                                               const float* __restrict__ cc,
                                               const float* __restrict__ ttime,
                                               const int*   __restrict__ tidx,
                                               int n, float* __restrict__ out)
{
    __shared__ ulonglong2 sB[KC * 2];
    __shared__ float4 sBs[KC];
    __shared__ float sQ[KC];
    __shared__ float sQsum;
    __shared__ float red[16];
    __shared__ int sLast;

    int t = threadIdx.x;
    for (int j = t; j < KC * 2; j += TPB3) sB[j] = g_B[j];
    for (int j = t; j < KC; j += TPB3) { sBs[j] = g_Bs[j]; sQ[j] = g_q[j]; }
    if (t == 0) sQsum = g_s[7];
    __syncthreads();

    int i0 = blockIdx.x * TPB3 + t;
    int i1 = i0 + NT3;

    float x00 = 0.f, x01 = 0.f, x02 = 0.f, q0 = 0.f; int k0 = -1;
    float x10 = 0.f, x11 = 0.f, x12 = 0.f, q1 = 0.f; int k1 = -1;
    if (i0 < n) {
        x00 = cc[3 * i0]; x01 = cc[3 * i0 + 1]; x02 = cc[3 * i0 + 2];
        float b = clip_beta(pbeta[i0]); float a = atanhf(b);
        q0 = (a * a + Q_MIN) * ttime[i0];
        k0 = tidx[i0];
    }
    if (i1 < n) {
        x10 = cc[3 * i1]; x11 = cc[3 * i1 + 1]; x12 = cc[3 * i1 + 2];
        float b = clip_beta(pbeta[i1]); float a = atanhf(b);
        q1 = (a * a + Q_MIN) * ttime[i1];
        k1 = tidx[i1];
    }
    float cie0 = fmaf(x02, x02, fmaf(x01, x01, fmaf(x00, x00, 1e-9f)));
    float cie1 = fmaf(x12, x12, fmaf(x11, x11, fmaf(x10, x10, 1e-9f)));

    unsigned long long x0p = packf2(x00, x10);
    unsigned long long x1p = packf2(x01, x11);
    unsigned long long x2p = packf2(x02, x12);
    unsigned long long cip = packf2(cie0, cie1);

    float acc0 = 0.0f, acc1 = 0.0f;
    #pragma unroll 4
    for (int k = 0; k < KC; k++) {
        ulonglong2 b0 = sB[2 * k];        // {Bx,Bx},{By,By}
        ulonglong2 b1 = sB[2 * k + 1];    // {Bz,Bz},{Bw,Bw}
        float qk = sQ[k];
        unsigned long long tt = fma2(b0.x, x0p, cip);
        tt = fma2(b0.y, x1p, tt);
        tt = fma2(b1.x, x2p, tt);
        unsigned long long d2p = add2(tt, b1.y);
        float s0 = fsqrt_ap(lo32(d2p));
        float s1 = fsqrt_ap(hi32(d2p));
        acc0 = fmaf(qk, fminf(s0, 1.0f), acc0);
        acc1 = fmaf(qk, fminf(s1, 1.0f), acc1);
    }

    float Qsum = sQsum;
    float att = 0.0f, rep = 0.0f;
    {
        float def = Qsum - acc0;
        if (k0 >= 0) {
            float4 Bm = sBs[k0]; float qm = sQ[k0];
            float tm = fmaf(Bm.x, x00, cie0); tm = fmaf(Bm.y, x01, tm); tm = fmaf(Bm.z, x02, tm);
            float d2e = tm + Bm.w;
            float m = fminf(fsqrt_ap(d2e), 1.0f);
            def -= qm * (1.0f - m);
            att += (d2e - 1e-9f) * qm * q0;
        }
        rep += q0 * def;
    }
    {
        float def = Qsum - acc1;
        if (k1 >= 0) {
            float4 Bm = sBs[k1]; float qm = sQ[k1];
            float tm = fmaf(Bm.x, x10, cie1); tm = fmaf(Bm.y, x11, tm); tm = fmaf(Bm.z, x12, tm);
            float d2e = tm + Bm.w;
            float m = fminf(fsqrt_ap(d2e), 1.0f);
            def -= qm * (1.0f - m);
            att += (d2e - 1e-9f) * qm * q1;
        }
        rep += q1 * def;
    }

    // block reduce (8 warps)
    float wa = warp_sum(att), wr = warp_sum(rep);
    int wid = t >> 5, lid = t & 31;
    if (lid == 0) { red[wid] = wa; red[8 + wid] = wr; }
    __syncthreads();
    if (wid == 0) {
        float va = (lid < 8) ? red[lid]     : 0.0f;
        float vr = (lid < 8) ? red[8 + lid] : 0.0f;
        va = warp_sum(va); vr = warp_sum(vr);
        if (lid == 0) { atomicAdd(&g_s[0], va); atomicAdd(&g_s[1], vr); }
    }

    // finisher: compute output, re-zero att/rep accumulators for next replay
    if (t == 0) {
        __threadfence();
        unsigned old = atomicAdd(&g_done2, 1u);
        sLast = (old == gridDim.x - 1) ? 1 : 0;
    }
    __syncthreads();
    if (sLast && t == 0) {
        __threadfence();
        volatile float* vs = g_s;
        float s0 = vs[0], s1 = vs[1], s2 = vs[2], s3 = vs[3];
        float s4 = vs[4], s5 = vs[5], s6 = vs[6];
        float nobj = fmaxf(s6, 1.0f);
        float ncnt = fmaxf(s5, 1.0f);
        out[0] = (s0 + s1) / (float)n + s2 / nobj + s4 / ncnt + s3 / nobj;
        g_s[0] = 0.0f; g_s[1] = 0.0f;
        g_done2 = 0u;
    }
}

// ---------------- launcher ----------------
// metadata order: 0 pred_beta, 1 pred_ccoords, 2 pred_energy, 3 pred_pos,
// 4 pred_time, 5 pred_id, 6 t_idx, 7 t_energy, 8 t_pos, 9 t_time, 10 t_pid, 11 rowsplits
extern "C" void kernel_launch(void* const* d_in, const int* in_sizes, int n_in,
                              void* d_out, int out_size) {
    const float* pbeta   = (const float*)d_in[0];
    const float* cc      = (const float*)d_in[1];
    const float* penergy = (const float*)d_in[2];
    const float* ppos    = (const float*)d_in[3];
    const int*   tidx    = (const int*)  d_in[6];
    const float* tenergy = (const float*)d_in[7];
    const float* tpos    = (const float*)d_in[8];
    const float* ttime   = (const float*)d_in[9];
    float* out = (float*)d_out;

    int n = in_sizes[0];
    int blocks1 = (n + TPB1 - 1) / TPB1;

    k_pass1<<<blocks1, TPB1>>>(pbeta, tenergy, penergy, tpos, ppos, tidx, cc, ttime, n);
    k_main<<<NB3, TPB3>>>(pbeta, cc, ttime, tidx, n, out);
}

// round 5
// speedup vs baseline: 1.3667x; 1.1156x over previous
#include <cuda_runtime.h>
#include <math.h>

#define KC 192
#define KP (KC / 2)        // 96 cluster pairs
#define Q_MIN 0.5f
#define TPB1 256
#define TPB3 256

// ---------------- device scratch (no allocations allowed) ----------------
// Atomic targets 1024B-strided so each lands on a distinct L2 partition.
__device__ unsigned long long g_key[KC * 128];
__device__ float g_wsum[KC * 256];
__device__ float g_wps [KC * 256];
__device__ float g_nacc[32 * 256];

// packed cluster pairs: g_Bp[2j] = {{Bx2j,Bx2j+1},{By2j,By2j+1}}, g_Bp[2j+1] = {{Bz..},{Bw..}}
__device__ ulonglong2 g_Bp[KP * 2];
__device__ float2     g_qp[KP];

// 0 att, 1 rep, 2 minb, 3 pay, 4 noise_sum, 5 noise_cnt, 6 nobj, 7 Qsum
__device__ float g_s[8];
__device__ unsigned g_done1, g_done2;

// ---------------- helpers ----------------
__device__ __forceinline__ float warp_sum(float v) {
    #pragma unroll
    for (int o = 16; o > 0; o >>= 1) v += __shfl_down_sync(0xFFFFFFFFu, v, o);
    return v;
}
__device__ __forceinline__ float clip_beta(float b) {
    return fminf(fmaxf(b, 1e-4f), 1.0f - 1e-4f);
}
__device__ __forceinline__ unsigned long long fma2(unsigned long long a, unsigned long long b, unsigned long long c) {
    unsigned long long d;
    asm("fma.rn.f32x2 %0, %1, %2, %3;" : "=l"(d) : "l"(a), "l"(b), "l"(c));
    return d;
}
__device__ __forceinline__ unsigned long long add2(unsigned long long a, unsigned long long b) {
    unsigned long long d;
    asm("add.rn.f32x2 %0, %1, %2;" : "=l"(d) : "l"(a), "l"(b));
    return d;
}
__device__ __forceinline__ unsigned long long packf2(float lo, float hi) {
    return (unsigned long long)__float_as_uint(lo) | ((unsigned long long)__float_as_uint(hi) << 32);
}
__device__ __forceinline__ float lo32(unsigned long long v) { return __uint_as_float((unsigned)v); }
__device__ __forceinline__ float hi32(unsigned long long v) { return __uint_as_float((unsigned)(v >> 32)); }
__device__ __forceinline__ float fsqrt_ap(float x) {
    float r; asm("sqrt.approx.f32 %0, %1;" : "=f"(r) : "f"(x)); return r;
}

// ---------------- pass 1: per-point reductions + fused cluster stage ----------------
__global__ void __launch_bounds__(TPB1) k_pass1(const float* __restrict__ pbeta,
                        const float* __restrict__ tenergy,
                        const float* __restrict__ penergy,
                        const float* __restrict__ tpos,
                        const float* __restrict__ ppos,
                        const int*   __restrict__ tidx,
                        const float* __restrict__ cc,
                        const float* __restrict__ ttime,
                        int n)
{
    int t = threadIdx.x;
    int i = blockIdx.x * TPB1 + t;
    float nsum = 0.0f, ncnt = 0.0f;
    if (i < n) {
        float b = clip_beta(pbeta[i]);
        int k = tidx[i];
        if (k >= 0) {
            float a = atanhf(b);
            float w = a * a;
            unsigned long long key =
                ((unsigned long long)__float_as_uint(b) << 32) |
                (unsigned long long)(0xFFFFFFFFu - (unsigned)i);
            atomicMax(&g_key[k * 128], key);
            atomicAdd(&g_wsum[k * 256], w);

            float te = tenergy[i], pe = penergy[i];
            float de = te - pe;
            float el = (de * de) / (te * te);

            float2 tp = ((const float2*)tpos)[i];
            float2 pp = ((const float2*)ppos)[i];
            float d0 = tp.x - pp.x, d1 = tp.y - pp.y;
            float pl = (d0 * d0) / (tp.x * tp.x) + (d1 * d1) / (tp.y * tp.y);

            atomicAdd(&g_wps[k * 256], w * (el + pl));
        } else {
            nsum = b; ncnt = 1.0f;
        }
    }

    // block-reduce noise, scatter to 32 padded slots
    __shared__ float nred[2][8];
    {
        float ws = warp_sum(nsum), wc = warp_sum(ncnt);
        int wid = t >> 5, lid = t & 31;
        if (lid == 0) { nred[0][wid] = ws; nred[1][wid] = wc; }
        __syncthreads();
        if (wid == 0) {
            float vs = (lid < 8) ? nred[0][lid] : 0.0f;
            float vc = (lid < 8) ? nred[1][lid] : 0.0f;
            vs = warp_sum(vs); vc = warp_sum(vc);
            if (lid == 0 && (vs != 0.0f || vc != 0.0f)) {
                int s = (blockIdx.x & 31) * 256;
                atomicAdd(&g_nacc[s], vs);
                atomicAdd(&g_nacc[s + 1], vc);
            }
        }
    }

    // finisher block: fused cluster stage
    __shared__ int sLast;
    if (t == 0) {
        __threadfence();
        unsigned old = atomicAdd(&g_done1, 1u);
        sLast = (old == gridDim.x - 1) ? 1 : 0;
    }
    __syncthreads();
    if (!sLast) return;
    if (t == 0) __threadfence();
    __syncthreads();

    __shared__ float sb[5][KC];   // Bx By Bz Bw q staging for pair packing
    float minb = 0.0f, pay = 0.0f, nobj = 0.0f, qs = 0.0f;
    if (t < KC) {
        unsigned long long key = g_key[t * 128];
        float Bx = 0.f, By = 0.f, Bz = 0.f, Bw = 0.f, q = 0.f;
        if (key != 0ull) {
            unsigned idx = 0xFFFFFFFFu - (unsigned)(key & 0xFFFFFFFFull);
            float b = clip_beta(pbeta[idx]);
            float a = atanhf(b);
            q = (a * a + Q_MIN) * ttime[idx];
            float ax = cc[3 * idx], ay = cc[3 * idx + 1], az = cc[3 * idx + 2];
            Bx = -2.0f * ax; By = -2.0f * ay; Bz = -2.0f * az;
            Bw = ax * ax + ay * ay + az * az;
            nobj = 1.0f;
            minb = 1.0f - b;
            qs = q;
            pay = g_wps[t * 256] / (g_wsum[t * 256] + 1e-9f);
        }
        sb[0][t] = Bx; sb[1][t] = By; sb[2][t] = Bz; sb[3][t] = Bw; sb[4][t] = q;
        // reset pass-1 scratch for next replay
        g_key[t * 128] = 0ull;
        g_wsum[t * 256] = 0.0f;
        g_wps[t * 256] = 0.0f;
    }
    // noise slot aggregation + reset
    if (t < 32) {
        float vs = g_nacc[t * 256];
        float vc = g_nacc[t * 256 + 1];
        g_nacc[t * 256] = 0.0f;
        g_nacc[t * 256 + 1] = 0.0f;
        vs = warp_sum(vs); vc = warp_sum(vc);
        if (t == 0) { g_s[4] = vs; g_s[5] = vc; g_done1 = 0u; }
    }
    __syncthreads();
    // pack cluster pairs
    if (t < KP) {
        int a = 2 * t, b = 2 * t + 1;
        g_Bp[2 * t]     = make_ulonglong2(packf2(sb[0][a], sb[0][b]), packf2(sb[1][a], sb[1][b]));
        g_Bp[2 * t + 1] = make_ulonglong2(packf2(sb[2][a], sb[2][b]), packf2(sb[3][a], sb[3][b]));
        g_qp[t] = make_float2(sb[4][a], sb[4][b]);
    }
    // reduce minb / pay / nobj / Qsum over 8 warps
    __shared__ float red[4][8];
    float wm = warp_sum(minb), wp = warp_sum(pay), wn = warp_sum(nobj), wq = warp_sum(qs);
    int wid = t >> 5, lid = t & 31;
    if (lid == 0) { red[0][wid] = wm; red[1][wid] = wp; red[2][wid] = wn; red[3][wid] = wq; }
    __syncthreads();
    if (wid == 0) {
        float vm = (lid < 8) ? red[0][lid] : 0.0f;
        float vp = (lid < 8) ? red[1][lid] : 0.0f;
        float vn = (lid < 8) ? red[2][lid] : 0.0f;
        float vq = (lid < 8) ? red[3][lid] : 0.0f;
        vm = warp_sum(vm); vp = warp_sum(vp); vn = warp_sum(vn); vq = warp_sum(vq);
        if (lid == 0) { g_s[2] = vm; g_s[3] = vp; g_s[6] = vn; g_s[7] = vq; }
    }
}

// ---------------- pass 2: O(N*K) pair pass, 1 point/thread, 2 clusters/iter ----------------
__global__ void __launch_bounds__(TPB3) k_main(const float* __restrict__ pbeta,
                                               const float* __restrict__ cc,
                                               const float* __restrict__ ttime,
                                               const int*   __restrict__ tidx,
                                               int n, float* __restrict__ out)
{
    __shared__ ulonglong2 sB[KP * 2];
    __shared__ float2 sQp[KP];
    __shared__ float sQsum;
    __shared__ float red[16];
    __shared__ int sLast;

    int t = threadIdx.x;
    for (int j = t; j < KP * 2; j += TPB3) sB[j] = g_Bp[j];
    for (int j = t; j < KP; j += TPB3) sQp[j] = g_qp[j];
    if (t == 0) sQsum = g_s[7];
    __syncthreads();

    int i = blockIdx.x * TPB3 + t;

    float x0 = 0.f, x1 = 0.f, x2 = 0.f, q = 0.f; int km = -1;
    if (i < n) {
        x0 = cc[3 * i]; x1 = cc[3 * i + 1]; x2 = cc[3 * i + 2];
        float b = clip_beta(pbeta[i]); float a = atanhf(b);
        q = (a * a + Q_MIN) * ttime[i];
        km = tidx[i];
    }
    float ci = fmaf(x2, x2, fmaf(x1, x1, fmaf(x0, x0, 1e-9f)));

    unsigned long long x0d = packf2(x0, x0);
    unsigned long long x1d = packf2(x1, x1);
    unsigned long long x2d = packf2(x2, x2);
    unsigned long long cid = packf2(ci, ci);

    float accA = 0.0f, accB = 0.0f;
    #pragma unroll 4
    for (int j = 0; j < KP; j++) {
        ulonglong2 ba = sB[2 * j];       // {Bx lo,hi},{By lo,hi}
        ulonglong2 bb = sB[2 * j + 1];   // {Bz lo,hi},{Bw lo,hi}
        float2 qp = sQp[j];
        unsigned long long tt = fma2(ba.x, x0d, cid);
        tt = fma2(ba.y, x1d, tt);
        tt = fma2(bb.x, x2d, tt);
        unsigned long long d2p = add2(tt, bb.y);
        // saturate clamps cancellation-negative d2 to 0 (sqrt(neg) would be NaN)
        float da = __saturatef(lo32(d2p));
        float db = __saturatef(hi32(d2p));
        accA = fmaf(qp.x, fsqrt_ap(da), accA);
        accB = fmaf(qp.y, fsqrt_ap(db), accB);
    }

    float att = 0.0f, rep = 0.0f;
    {
        float def = sQsum - (accA + accB);
        if (km >= 0) {
            int j = km >> 1; int hi = km & 1;
            ulonglong2 ba = sB[2 * j], bb = sB[2 * j + 1];
            float Bx = hi ? hi32(ba.x) : lo32(ba.x);
            float By = hi ? hi32(ba.y) : lo32(ba.y);
            float Bz = hi ? hi32(bb.x) : lo32(bb.x);
            float Bw = hi ? hi32(bb.y) : lo32(bb.y);
            float2 qp = sQp[j];
            float qm = hi ? qp.y : qp.x;
            float tm = fmaf(Bx, x0, ci); tm = fmaf(By, x1, tm); tm = fmaf(Bz, x2, tm);
            float d2e = tm + Bw;
            float m = fsqrt_ap(__saturatef(d2e));
            def -= qm * (1.0f - m);
            att = (d2e - 1e-9f) * qm * q;
        }
        rep = q * def;
    }

    // block reduce (8 warps)
    float wa = warp_sum(att), wr = warp_sum(rep);
    int wid = t >> 5, lid = t & 31;
    if (lid == 0) { red[wid] = wa; red[8 + wid] = wr; }
    __syncthreads();
    if (wid == 0) {
        float va = (lid < 8) ? red[lid]     : 0.0f;
        float vr = (lid < 8) ? red[8 + lid] : 0.0f;
        va = warp_sum(va); vr = warp_sum(vr);
        if (lid == 0) { atomicAdd(&g_s[0], va); atomicAdd(&g_s[1], vr); }
    }

    // finisher: compute output, re-zero accumulators for next replay
    if (t == 0) {
        __threadfence();
        unsigned old = atomicAdd(&g_done2, 1u);
        sLast = (old == gridDim.x - 1) ? 1 : 0;
    }
    __syncthreads();
    if (sLast && t == 0) {
        __threadfence();
        volatile float* vs = g_s;
        float s0 = vs[0], s1 = vs[1], s2 = vs[2], s3 = vs[3];
        float s4 = vs[4], s5 = vs[5], s6 = vs[6];
        float nobj = fmaxf(s6, 1.0f);
        float ncnt = fmaxf(s5, 1.0f);
        out[0] = (s0 + s1) / (float)n + s2 / nobj + s4 / ncnt + s3 / nobj;
        g_s[0] = 0.0f; g_s[1] = 0.0f;
        g_done2 = 0u;
    }
}

// ---------------- launcher ----------------
// metadata order: 0 pred_beta, 1 pred_ccoords, 2 pred_energy, 3 pred_pos,
// 4 pred_time, 5 pred_id, 6 t_idx, 7 t_energy, 8 t_pos, 9 t_time, 10 t_pid, 11 rowsplits
extern "C" void kernel_launch(void* const* d_in, const int* in_sizes, int n_in,
                              void* d_out, int out_size) {
    const float* pbeta   = (const float*)d_in[0];
    const float* cc      = (const float*)d_in[1];
    const float* penergy = (const float*)d_in[2];
    const float* ppos    = (const float*)d_in[3];
    const int*   tidx    = (const int*)  d_in[6];
    const float* tenergy = (const float*)d_in[7];
    const float* tpos    = (const float*)d_in[8];
    const float* ttime   = (const float*)d_in[9];
    float* out = (float*)d_out;

    int n = in_sizes[0];
    int blocks1 = (n + TPB1 - 1) / TPB1;
    int blocks3 = (n + TPB3 - 1) / TPB3;

    k_pass1<<<blocks1, TPB1>>>(pbeta, tenergy, penergy, tpos, ppos, tidx, cc, ttime, n);
    k_main<<<blocks3, TPB3>>>(pbeta, cc, ttime, tidx, n, out);
}